// round 12
// baseline (speedup 1.0000x reference)
#include <cuda_runtime.h>
#include <math.h>

#define NN 100000
#define EE 1600000
#define CC 128
#define HH 64
#define GG 512
#define KMAX 32
#define MM 32

__device__ float4 g_agg1[NN * (CC / 4)];
__device__ float g_out1[NN * HH];
__device__ float g_raw[NN];
__device__ float g_score[NN];
__device__ unsigned int g_bits[(NN + 31) / 32];
__device__ float g_klval[GG];
__device__ float g_cntval[GG];
__device__ float g_go[GG * HH];
__device__ int g_kept[GG * KMAX];
__device__ int g_keptcnt[GG];
__device__ int g_elist[EE];
__device__ int g_n2;

__device__ __forceinline__ void red_add_v4(float4* a, float4 v) {
    asm volatile("red.global.add.v4.f32 [%0], {%1,%2,%3,%4};"
                 :: "l"(a), "f"(v.x), "f"(v.y), "f"(v.z), "f"(v.w) : "memory");
}
__device__ __forceinline__ bool testbit(int n) {
    return (__ldg(&g_bits[n >> 5]) >> (n & 31)) & 1u;
}

// ---------------- k_raw: dedicated x-streaming dot kernel ----------
__global__ void __launch_bounds__(256, 8) k_raw(const float4* __restrict__ x4,
                                                const float4* __restrict__ pw4) {
    if (blockIdx.x == 0 && threadIdx.x == 0) g_n2 = 0;
    int gw = (blockIdx.x * blockDim.x + threadIdx.x) >> 5;
    int lane = threadIdx.x & 31;
    int nw = (gridDim.x * blockDim.x) >> 5;
    float4 w = pw4[lane];
    for (int n0 = gw * 4; n0 < NN; n0 += nw * 4) {
        float s0 = 0.f, s1 = 0.f, s2 = 0.f, s3 = 0.f;
        int lim = NN - n0;
        const float4* base = &x4[(size_t)n0 * 32 + lane];
        float4 v0 = __ldcs(base);
        s0 = v0.x * w.x + v0.y * w.y + v0.z * w.z + v0.w * w.w;
        if (lim > 1) { float4 v = __ldcs(base + 32);  s1 = v.x * w.x + v.y * w.y + v.z * w.z + v.w * w.w; }
        if (lim > 2) { float4 v = __ldcs(base + 64);  s2 = v.x * w.x + v.y * w.y + v.z * w.z + v.w * w.w; }
        if (lim > 3) { float4 v = __ldcs(base + 96);  s3 = v.x * w.x + v.y * w.y + v.z * w.z + v.w * w.w; }
        #pragma unroll
        for (int o = 16; o; o >>= 1) {
            s0 += __shfl_down_sync(0xffffffffu, s0, o);
            s1 += __shfl_down_sync(0xffffffffu, s1, o);
            s2 += __shfl_down_sync(0xffffffffu, s2, o);
            s3 += __shfl_down_sync(0xffffffffu, s3, o);
        }
        if (lane == 0) {
            g_raw[n0] = s0;
            if (lim > 1) g_raw[n0 + 1] = s1;
            if (lim > 2) g_raw[n0 + 2] = s2;
            if (lim > 3) g_raw[n0 + 3] = s3;
        }
    }
}

// ---------------- k_soft: per-graph softmax/topk over precomputed raw ----------
__global__ void k_soft(const int* __restrict__ batch, const float* __restrict__ attn) {
    int b = blockIdx.x;
    int t = threadIdx.x;
    __shared__ float sraw[1024];
    __shared__ float red[256];
    __shared__ int s_se[2];
    __shared__ int s_kcnt;
    if (t == 0) s_kcnt = 0;
    if (t < 2) {
        int target = b + t;
        int lo = 0, hi = NN;
        while (lo < hi) { int mid = (lo + hi) >> 1; if (batch[mid] < target) lo = mid + 1; else hi = mid; }
        s_se[t] = lo;
    }
    for (int k = t; k < HH; k += 256) g_go[b * HH + k] = 0.f;
    __syncthreads();
    int start = s_se[0];
    int len = s_se[1] - start;

    for (int q = t; q < len; q += 256) sraw[q] = g_raw[start + q];
    __syncthreads();

    float m = -INFINITY;
    for (int q = t; q < len; q += 256) m = fmaxf(m, sraw[q]);
    red[t] = m; __syncthreads();
    for (int o = 128; o; o >>= 1) { if (t < o) red[t] = fmaxf(red[t], red[t + o]); __syncthreads(); }
    m = red[0]; __syncthreads();

    float sum = 0.f;
    for (int q = t; q < len; q += 256) sum += expf(sraw[q] - m);
    red[t] = sum; __syncthreads();
    for (int o = 128; o; o >>= 1) { if (t < o) red[t] += red[t + o]; __syncthreads(); }
    float z = red[0]; __syncthreads();

    float smax = 1.0f / z;   // score of the argmax node (exp(0)/z)
    float thresh = fminf(smax - 1e-7f, 0.05f);

    float kl = 0.f, cnt = 0.f;
    for (int q = t; q < len; q += 256) {
        float s = expf(sraw[q] - m) / z;
        int node = start + q;
        if (s > thresh) {
            cnt += 1.f;
            float a = attn[node];
            kl += a * (logf(a) - logf(s + 1e-14f));
            g_score[node] = s;
            int slot = atomicAdd(&s_kcnt, 1);
            if (slot < KMAX) {
                g_kept[b * KMAX + slot] = node;
                atomicOr(&g_bits[node >> 5], 1u << (node & 31));
                float4 zz = make_float4(0.f, 0.f, 0.f, 0.f);
                float4* a1 = &g_agg1[(size_t)node * 32];
                #pragma unroll
                for (int qq = 0; qq < 32; qq++) a1[qq] = zz;
            }
        }
    }
    red[t] = kl; __syncthreads();
    for (int o = 128; o; o >>= 1) { if (t < o) red[t] += red[t + o]; __syncthreads(); }
    if (t == 0) g_klval[b] = red[0];
    __syncthreads();
    red[t] = cnt; __syncthreads();
    for (int o = 128; o; o >>= 1) { if (t < o) red[t] += red[t + o]; __syncthreads(); }
    if (t == 0) {
        g_cntval[b] = red[0];
        g_keptcnt[b] = (s_kcnt < KMAX) ? s_kcnt : KMAX;
    }
}

// ---------------- k_edges: scatter-1 + both-kept edge list + ratio ----------
#define EPB 1024
__global__ void k_edges(const int* __restrict__ ei, const float4* __restrict__ x4,
                        float* __restrict__ out) {
    __shared__ int list[EPB];
    __shared__ int scnt;
    __shared__ float rsum[256];
    if (threadIdx.x == 0) scnt = 0;
    __syncthreads();
    int q = blockIdx.x * 256 + threadIdx.x;
    if (q < EE / 4) {
        int4 d4 = ((const int4*)(ei + EE))[q];
        int e0 = q * 4;
        int dd[4] = {d4.x, d4.y, d4.z, d4.w};
        #pragma unroll
        for (int k = 0; k < 4; k++) {
            int d = dd[k];
            if (testbit(d)) {
                int e = e0 + k;
                int p = atomicAdd(&scnt, 1);
                list[p] = e;
                int s = ei[e];
                if (testbit(s)) {
                    int w = atomicAdd(&g_n2, 1);
                    g_elist[w] = e;
                }
            }
        }
    }
    __syncthreads();
    int nk = scnt;
    int wid = threadIdx.x >> 5;
    int lane = threadIdx.x & 31;
    for (int i = wid; i < nk; i += 8) {
        int ee = list[i];
        int s = ei[ee];
        int d = ei[EE + ee];
        red_add_v4(&g_agg1[(size_t)d * 32 + lane], x4[(size_t)s * 32 + lane]);
    }
    if (blockIdx.x == 0) {
        __syncthreads();
        rsum[threadIdx.x] = g_cntval[threadIdx.x] + g_cntval[threadIdx.x + 256];
        __syncthreads();
        for (int o = 128; o; o >>= 1) { if (threadIdx.x < o) rsum[threadIdx.x] += rsum[threadIdx.x + o]; __syncthreads(); }
        if (threadIdx.x == 0) out[2 * GG] = rsum[0] / (float)NN;
    }
}

// ---------------- k_gin1: one block per (graph, kept-slot) ------------------
// 256 threads = 64 outputs (j) x 4 k-quarters (q).
__global__ void __launch_bounds__(256, 8) k_gin1(
    const float* __restrict__ x,
    const float* __restrict__ W1, const float* __restrict__ b1,
    const float* __restrict__ W2, const float* __restrict__ b2)
{
    int g = blockIdx.x;
    int s = blockIdx.y;
    if (s >= g_keptcnt[g]) return;
    int n = g_kept[g * KMAX + s];
    int t = threadIdx.x;
    int j = t & 63;
    int q = t >> 6;
    __shared__ float sv[CC];
    __shared__ float sp[4][HH];
    __shared__ float sh1[HH];

    if (t < CC) sv[t] = x[(size_t)n * CC + t] + ((const float*)g_agg1)[(size_t)n * CC + t];
    __syncthreads();
    float acc = (q == 0) ? __ldg(&b1[j]) : 0.f;
    const float* wp = W1 + (size_t)(q * 32) * HH + j;
    #pragma unroll
    for (int k = 0; k < 32; k++) acc = fmaf(sv[q * 32 + k], __ldg(&wp[(size_t)k * HH]), acc);
    sp[q][j] = acc;
    __syncthreads();
    if (t < HH) sh1[t] = fmaxf((sp[0][t] + sp[1][t]) + (sp[2][t] + sp[3][t]), 0.f);
    __syncthreads();
    float a2 = (q == 0) ? __ldg(&b2[j]) : 0.f;
    const float* wp2 = W2 + (size_t)(q * 16) * HH + j;
    #pragma unroll
    for (int k = 0; k < 16; k++) a2 = fmaf(sh1[q * 16 + k], __ldg(&wp2[(size_t)k * HH]), a2);
    sp[q][j] = a2;
    __syncthreads();
    if (t < HH)
        g_out1[(size_t)n * HH + t] =
            fmaxf((sp[0][t] + sp[1][t]) + (sp[2][t] + sp[3][t]), 0.f) * g_score[n];
}

// ---------------- k_gin2: one block per (graph, kept-slot) ------------------
// Gathers agg2 for its node from the both-kept edge list (dst == n), runs MLP2,
// atomically accumulates into g_go[g]. Also self-cleans the node's kept bit.
__global__ void __launch_bounds__(256, 8) k_gin2(
    const int* __restrict__ ei,
    const float* __restrict__ W3, const float* __restrict__ b3,
    const float* __restrict__ W4, const float* __restrict__ b4)
{
    int g = blockIdx.x;
    int s = blockIdx.y;
    if (s >= g_keptcnt[g]) return;
    int n = g_kept[g * KMAX + s];
    int t = threadIdx.x;
    int j = t & 63;
    int q = t >> 6;
    __shared__ float sv[HH];
    __shared__ float sp[4][HH];
    __shared__ float sh1[HH];
    __shared__ int s_msrc[MM];
    __shared__ int s_nm;
    if (t == 0) s_nm = 0;
    __syncthreads();

    // find both-kept edges whose dst is exactly this node
    int n2 = g_n2;
    for (int i = t; i < n2; i += 256) {
        int e = g_elist[i];
        if (ei[EE + e] == n) {
            int p = atomicAdd(&s_nm, 1);
            if (p < MM) s_msrc[p] = ei[e];
        }
    }
    __syncthreads();
    int nm = (s_nm < MM) ? s_nm : MM;
    if (t < HH) {
        float v = g_out1[(size_t)n * HH + t];
        for (int mI = 0; mI < nm; mI++)
            v += g_out1[(size_t)s_msrc[mI] * HH + t];
        sv[t] = v;
    }
    __syncthreads();

    float acc = (q == 0) ? __ldg(&b3[j]) : 0.f;
    const float* wp = W3 + (size_t)(q * 16) * HH + j;
    #pragma unroll
    for (int k = 0; k < 16; k++) acc = fmaf(sv[q * 16 + k], __ldg(&wp[(size_t)k * HH]), acc);
    sp[q][j] = acc;
    __syncthreads();
    if (t < HH) sh1[t] = fmaxf((sp[0][t] + sp[1][t]) + (sp[2][t] + sp[3][t]), 0.f);
    __syncthreads();
    float a2 = (q == 0) ? __ldg(&b4[j]) : 0.f;
    const float* wp2 = W4 + (size_t)(q * 16) * HH + j;
    #pragma unroll
    for (int k = 0; k < 16; k++) a2 = fmaf(sh1[q * 16 + k], __ldg(&wp2[(size_t)k * HH]), a2);
    sp[q][j] = a2;
    __syncthreads();
    if (t < HH)
        atomicAdd(&g_go[g * HH + t],
                  fmaxf((sp[0][t] + sp[1][t]) + (sp[2][t] + sp[3][t]), 0.f));
    // self-clean this node's kept bit (once per node)
    if (t == 0) atomicAnd(&g_bits[n >> 5], ~(1u << (n & 31)));
}

// ---------------- k_final: pred + attn_loss ----------------
__global__ void k_final(const float* __restrict__ Wl, const float* __restrict__ bl,
                        float* __restrict__ out) {
    int g = threadIdx.x + blockIdx.x * blockDim.x;
    if (g < GG) {
        float p = bl[0];
        #pragma unroll 8
        for (int k = 0; k < HH; k++) p = fmaf(g_go[g * HH + k], __ldg(&Wl[k]), p);
        out[g] = p;
        out[GG + g] = g_klval[g] / fmaxf(g_cntval[g], 1.0f);
    }
}

extern "C" void kernel_launch(void* const* d_in, const int* in_sizes, int n_in,
                              void* d_out, int out_size) {
    const float* x      = (const float*)d_in[0];
    const int*   ei     = (const int*)d_in[1];
    const int*   batch  = (const int*)d_in[2];
    const float* attn   = (const float*)d_in[3];
    const float* W1     = (const float*)d_in[4];
    const float* b1     = (const float*)d_in[5];
    const float* W2     = (const float*)d_in[6];
    const float* b2     = (const float*)d_in[7];
    const float* pool_w = (const float*)d_in[8];
    const float* W3     = (const float*)d_in[9];
    const float* b3     = (const float*)d_in[10];
    const float* W4     = (const float*)d_in[11];
    const float* b4     = (const float*)d_in[12];
    const float* Wl     = (const float*)d_in[13];
    const float* bl     = (const float*)d_in[14];
    float* out = (float*)d_out;

    k_raw<<<1184, 256>>>((const float4*)x, (const float4*)pool_w);
    k_soft<<<GG, 256>>>(batch, attn);
    k_edges<<<(EE + EPB - 1) / EPB, 256>>>(ei, (const float4*)x, out);
    dim3 gs(GG, KMAX);
    k_gin1<<<gs, 256>>>(x, W1, b1, W2, b2);
    k_gin2<<<gs, 256>>>(ei, W3, b3, W4, b4);
    k_final<<<2, 256>>>(Wl, bl, out);
}

// round 13
// speedup vs baseline: 1.1760x; 1.1760x over previous
#include <cuda_runtime.h>
#include <math.h>

#define NN 100000
#define EE 1600000
#define CC 128
#define HH 64
#define GG 512

__device__ float4 g_agg1[NN * (CC / 4)];
__device__ float4 g_agg2[NN * (HH / 4)];
__device__ float g_out1[NN * HH];
__device__ float g_raw[NN];
__device__ float g_score[NN];
__device__ unsigned int g_bits[(NN + 31) / 32];
__device__ float g_klval[GG];
__device__ float g_cntval[GG];
__device__ float g_go[GG * HH];
__device__ int g_flat[NN];     // flat kept-node list
__device__ int g_fgraph[NN];   // graph id per flat entry
__device__ int g_flatcnt;
__device__ int g_elist[EE];
__device__ int g_n2;

__device__ __forceinline__ void red_add_v4(float4* a, float4 v) {
    asm volatile("red.global.add.v4.f32 [%0], {%1,%2,%3,%4};"
                 :: "l"(a), "f"(v.x), "f"(v.y), "f"(v.z), "f"(v.w) : "memory");
}
__device__ __forceinline__ bool testbit(int n) {
    return (__ldg(&g_bits[n >> 5]) >> (n & 31)) & 1u;
}

// ---------------- k_raw: dedicated x-streaming dot kernel ----------
__global__ void __launch_bounds__(256, 8) k_raw(const float4* __restrict__ x4,
                                                const float4* __restrict__ pw4) {
    if (blockIdx.x == 0 && threadIdx.x == 0) { g_n2 = 0; g_flatcnt = 0; }
    int gw = (blockIdx.x * blockDim.x + threadIdx.x) >> 5;
    int lane = threadIdx.x & 31;
    int nw = (gridDim.x * blockDim.x) >> 5;
    float4 w = pw4[lane];
    for (int n0 = gw * 4; n0 < NN; n0 += nw * 4) {
        float s0 = 0.f, s1 = 0.f, s2 = 0.f, s3 = 0.f;
        int lim = NN - n0;
        const float4* base = &x4[(size_t)n0 * 32 + lane];
        float4 v0 = __ldcs(base);
        s0 = v0.x * w.x + v0.y * w.y + v0.z * w.z + v0.w * w.w;
        if (lim > 1) { float4 v = __ldcs(base + 32);  s1 = v.x * w.x + v.y * w.y + v.z * w.z + v.w * w.w; }
        if (lim > 2) { float4 v = __ldcs(base + 64);  s2 = v.x * w.x + v.y * w.y + v.z * w.z + v.w * w.w; }
        if (lim > 3) { float4 v = __ldcs(base + 96);  s3 = v.x * w.x + v.y * w.y + v.z * w.z + v.w * w.w; }
        #pragma unroll
        for (int o = 16; o; o >>= 1) {
            s0 += __shfl_down_sync(0xffffffffu, s0, o);
            s1 += __shfl_down_sync(0xffffffffu, s1, o);
            s2 += __shfl_down_sync(0xffffffffu, s2, o);
            s3 += __shfl_down_sync(0xffffffffu, s3, o);
        }
        if (lane == 0) {
            g_raw[n0] = s0;
            if (lim > 1) g_raw[n0 + 1] = s1;
            if (lim > 2) g_raw[n0 + 2] = s2;
            if (lim > 3) g_raw[n0 + 3] = s3;
        }
    }
}

// ---------------- k_soft: per-graph softmax/topk; builds flat kept list -----
__global__ void k_soft(const int* __restrict__ batch, const float* __restrict__ attn) {
    int b = blockIdx.x;
    int t = threadIdx.x;
    __shared__ float sraw[1024];
    __shared__ float red[256];
    __shared__ int s_se[2];
    if (t < 2) {
        int target = b + t;
        int lo = 0, hi = NN;
        while (lo < hi) { int mid = (lo + hi) >> 1; if (batch[mid] < target) lo = mid + 1; else hi = mid; }
        s_se[t] = lo;
    }
    for (int k = t; k < HH; k += 256) g_go[b * HH + k] = 0.f;
    __syncthreads();
    int start = s_se[0];
    int len = s_se[1] - start;

    for (int q = t; q < len; q += 256) sraw[q] = g_raw[start + q];
    __syncthreads();

    float m = -INFINITY;
    for (int q = t; q < len; q += 256) m = fmaxf(m, sraw[q]);
    red[t] = m; __syncthreads();
    for (int o = 128; o; o >>= 1) { if (t < o) red[t] = fmaxf(red[t], red[t + o]); __syncthreads(); }
    m = red[0]; __syncthreads();

    float sum = 0.f;
    for (int q = t; q < len; q += 256) sum += expf(sraw[q] - m);
    red[t] = sum; __syncthreads();
    for (int o = 128; o; o >>= 1) { if (t < o) red[t] += red[t + o]; __syncthreads(); }
    float z = red[0]; __syncthreads();

    float smax = 1.0f / z;   // score of the argmax node (exp(0)/z)
    float thresh = fminf(smax - 1e-7f, 0.05f);

    float kl = 0.f, cnt = 0.f;
    for (int q = t; q < len; q += 256) {
        float s = expf(sraw[q] - m) / z;
        int node = start + q;
        if (s > thresh) {
            cnt += 1.f;
            float a = attn[node];
            kl += a * (logf(a) - logf(s + 1e-14f));
            g_score[node] = s;
            int p = atomicAdd(&g_flatcnt, 1);
            g_flat[p] = node;
            g_fgraph[p] = b;
            atomicOr(&g_bits[node >> 5], 1u << (node & 31));
            float4 zz = make_float4(0.f, 0.f, 0.f, 0.f);
            float4* a1 = &g_agg1[(size_t)node * 32];
            #pragma unroll
            for (int qq = 0; qq < 32; qq++) a1[qq] = zz;
            float4* a2 = &g_agg2[(size_t)node * 16];
            #pragma unroll
            for (int qq = 0; qq < 16; qq++) a2[qq] = zz;
        }
    }
    red[t] = kl; __syncthreads();
    for (int o = 128; o; o >>= 1) { if (t < o) red[t] += red[t + o]; __syncthreads(); }
    if (t == 0) g_klval[b] = red[0];
    __syncthreads();
    red[t] = cnt; __syncthreads();
    for (int o = 128; o; o >>= 1) { if (t < o) red[t] += red[t + o]; __syncthreads(); }
    if (t == 0) g_cntval[b] = red[0];
}

// ---------------- k_edges: scatter-1 + both-kept edge list + ratio ----------
#define EPB 1024
__global__ void k_edges(const int* __restrict__ ei, const float4* __restrict__ x4,
                        float* __restrict__ out) {
    __shared__ int list[EPB];
    __shared__ int scnt;
    __shared__ float rsum[256];
    if (threadIdx.x == 0) scnt = 0;
    __syncthreads();
    int q = blockIdx.x * 256 + threadIdx.x;
    if (q < EE / 4) {
        int4 d4 = ((const int4*)(ei + EE))[q];
        int e0 = q * 4;
        int dd[4] = {d4.x, d4.y, d4.z, d4.w};
        #pragma unroll
        for (int k = 0; k < 4; k++) {
            int d = dd[k];
            if (testbit(d)) {
                int e = e0 + k;
                int p = atomicAdd(&scnt, 1);
                list[p] = e;
                int s = ei[e];
                if (testbit(s)) {
                    int w = atomicAdd(&g_n2, 1);
                    g_elist[w] = e;
                }
            }
        }
    }
    __syncthreads();
    int nk = scnt;
    int wid = threadIdx.x >> 5;
    int lane = threadIdx.x & 31;
    for (int i = wid; i < nk; i += 8) {
        int ee = list[i];
        int s = ei[ee];
        int d = ei[EE + ee];
        red_add_v4(&g_agg1[(size_t)d * 32 + lane], x4[(size_t)s * 32 + lane]);
    }
    if (blockIdx.x == 0) {
        __syncthreads();
        rsum[threadIdx.x] = g_cntval[threadIdx.x] + g_cntval[threadIdx.x + 256];
        __syncthreads();
        for (int o = 128; o; o >>= 1) { if (threadIdx.x < o) rsum[threadIdx.x] += rsum[threadIdx.x + o]; __syncthreads(); }
        if (threadIdx.x == 0) out[2 * GG] = rsum[0] / (float)NN;
    }
}

// ---------------- k_gin1: grid-stride over flat kept list -------------------
// 256 threads = 64 outputs (j) x 4 k-quarters (q); 8-deep load prefetch.
#define GINGRID 2048
__global__ void __launch_bounds__(256, 4) k_gin1(
    const float* __restrict__ x,
    const float* __restrict__ W1, const float* __restrict__ b1,
    const float* __restrict__ W2, const float* __restrict__ b2)
{
    int t = threadIdx.x;
    int j = t & 63;
    int q = t >> 6;
    __shared__ float sv[CC];
    __shared__ float sp[4][HH];
    __shared__ float sh1[HH];
    int fc = g_flatcnt;
    for (int i = blockIdx.x; i < fc; i += GINGRID) {
        int n = g_flat[i];
        if (t < CC) sv[t] = x[(size_t)n * CC + t] + ((const float*)g_agg1)[(size_t)n * CC + t];
        __syncthreads();
        float acc = (q == 0) ? __ldg(&b1[j]) : 0.f;
        const float* wp = W1 + (size_t)(q * 32) * HH + j;
        #pragma unroll
        for (int kb = 0; kb < 4; kb++) {
            float w[8];
            #pragma unroll
            for (int u = 0; u < 8; u++) w[u] = __ldg(&wp[(size_t)(kb * 8 + u) * HH]);
            #pragma unroll
            for (int u = 0; u < 8; u++) acc = fmaf(sv[q * 32 + kb * 8 + u], w[u], acc);
        }
        sp[q][j] = acc;
        __syncthreads();
        if (t < HH) sh1[t] = fmaxf((sp[0][t] + sp[1][t]) + (sp[2][t] + sp[3][t]), 0.f);
        __syncthreads();
        float a2 = (q == 0) ? __ldg(&b2[j]) : 0.f;
        const float* wp2 = W2 + (size_t)(q * 16) * HH + j;
        #pragma unroll
        for (int kb = 0; kb < 2; kb++) {
            float w[8];
            #pragma unroll
            for (int u = 0; u < 8; u++) w[u] = __ldg(&wp2[(size_t)(kb * 8 + u) * HH]);
            #pragma unroll
            for (int u = 0; u < 8; u++) a2 = fmaf(sh1[q * 16 + kb * 8 + u], w[u], a2);
        }
        sp[q][j] = a2;
        __syncthreads();
        if (t < HH)
            g_out1[(size_t)n * HH + t] =
                fmaxf((sp[0][t] + sp[1][t]) + (sp[2][t] + sp[3][t]), 0.f) * g_score[n];
        __syncthreads();
    }
}

// ---------------- k_scat2: scatter out1 over both-kept edges ----------------
__global__ void k_scat2(const int* __restrict__ ei) {
    int n2 = g_n2;
    int gw = (blockIdx.x * blockDim.x + threadIdx.x) >> 5;
    int lane = threadIdx.x & 31;
    int nw = (gridDim.x * blockDim.x) >> 5;
    for (int i = gw; i < n2; i += nw) {
        int e = g_elist[i];
        int s = ei[e];
        int d = ei[EE + e];
        if (lane < 16)
            red_add_v4(&g_agg2[(size_t)d * 16 + lane],
                       ((const float4*)g_out1)[(size_t)s * 16 + lane]);
    }
}

// ---------------- k_gin2: grid-stride over flat kept list -------------------
__global__ void __launch_bounds__(256, 4) k_gin2(
    const float* __restrict__ W3, const float* __restrict__ b3,
    const float* __restrict__ W4, const float* __restrict__ b4)
{
    int t = threadIdx.x;
    int j = t & 63;
    int q = t >> 6;
    __shared__ float sv[HH];
    __shared__ float sp[4][HH];
    __shared__ float sh1[HH];
    int fc = g_flatcnt;
    for (int i = blockIdx.x; i < fc; i += GINGRID) {
        int n = g_flat[i];
        int g = g_fgraph[i];
        if (t < HH)
            sv[t] = g_out1[(size_t)n * HH + t] + ((const float*)g_agg2)[(size_t)n * HH + t];
        __syncthreads();
        float acc = (q == 0) ? __ldg(&b3[j]) : 0.f;
        const float* wp = W3 + (size_t)(q * 16) * HH + j;
        #pragma unroll
        for (int kb = 0; kb < 2; kb++) {
            float w[8];
            #pragma unroll
            for (int u = 0; u < 8; u++) w[u] = __ldg(&wp[(size_t)(kb * 8 + u) * HH]);
            #pragma unroll
            for (int u = 0; u < 8; u++) acc = fmaf(sv[q * 16 + kb * 8 + u], w[u], acc);
        }
        sp[q][j] = acc;
        __syncthreads();
        if (t < HH) sh1[t] = fmaxf((sp[0][t] + sp[1][t]) + (sp[2][t] + sp[3][t]), 0.f);
        __syncthreads();
        float a2 = (q == 0) ? __ldg(&b4[j]) : 0.f;
        const float* wp2 = W4 + (size_t)(q * 16) * HH + j;
        #pragma unroll
        for (int kb = 0; kb < 2; kb++) {
            float w[8];
            #pragma unroll
            for (int u = 0; u < 8; u++) w[u] = __ldg(&wp2[(size_t)(kb * 8 + u) * HH]);
            #pragma unroll
            for (int u = 0; u < 8; u++) a2 = fmaf(sh1[q * 16 + kb * 8 + u], w[u], a2);
        }
        sp[q][j] = a2;
        __syncthreads();
        if (t < HH)
            atomicAdd(&g_go[g * HH + t],
                      fmaxf((sp[0][t] + sp[1][t]) + (sp[2][t] + sp[3][t]), 0.f));
        if (t == 0) atomicAnd(&g_bits[n >> 5], ~(1u << (n & 31)));   // self-clean
        __syncthreads();
    }
}

// ---------------- k_final: pred + attn_loss ----------------
__global__ void k_final(const float* __restrict__ Wl, const float* __restrict__ bl,
                        float* __restrict__ out) {
    int g = threadIdx.x + blockIdx.x * blockDim.x;
    if (g < GG) {
        float p = bl[0];
        #pragma unroll 8
        for (int k = 0; k < HH; k++) p = fmaf(g_go[g * HH + k], __ldg(&Wl[k]), p);
        out[g] = p;
        out[GG + g] = g_klval[g] / fmaxf(g_cntval[g], 1.0f);
    }
}

extern "C" void kernel_launch(void* const* d_in, const int* in_sizes, int n_in,
                              void* d_out, int out_size) {
    const float* x      = (const float*)d_in[0];
    const int*   ei     = (const int*)d_in[1];
    const int*   batch  = (const int*)d_in[2];
    const float* attn   = (const float*)d_in[3];
    const float* W1     = (const float*)d_in[4];
    const float* b1     = (const float*)d_in[5];
    const float* W2     = (const float*)d_in[6];
    const float* b2     = (const float*)d_in[7];
    const float* pool_w = (const float*)d_in[8];
    const float* W3     = (const float*)d_in[9];
    const float* b3     = (const float*)d_in[10];
    const float* W4     = (const float*)d_in[11];
    const float* b4     = (const float*)d_in[12];
    const float* Wl     = (const float*)d_in[13];
    const float* bl     = (const float*)d_in[14];
    float* out = (float*)d_out;

    k_raw<<<1184, 256>>>((const float4*)x, (const float4*)pool_w);
    k_soft<<<GG, 256>>>(batch, attn);
    k_edges<<<(EE + EPB - 1) / EPB, 256>>>(ei, (const float4*)x, out);
    k_gin1<<<GINGRID, 256>>>(x, W1, b1, W2, b2);
    k_scat2<<<16, 256>>>(ei);
    k_gin2<<<GINGRID, 256>>>(W3, b3, W4, b4);
    k_final<<<2, 256>>>(Wl, bl, out);
}

// round 14
// speedup vs baseline: 1.6769x; 1.4260x over previous
#include <cuda_runtime.h>
#include <math.h>

#define NN 100000
#define EE 1600000
#define CC 128
#define HH 64
#define GG 512
#define KMAX 32
#define MMAX 128

__device__ float4 g_agg1[NN * (CC / 4)];
__device__ float g_raw[NN];
__device__ float g_score[NN];
__device__ unsigned int g_bits[(NN + 31) / 32];
__device__ float g_klval[GG];
__device__ float g_cntval[GG];
__device__ int g_kept[GG * KMAX];
__device__ int g_keptcnt[GG];
__device__ int g_elist[EE];
__device__ int g_n2;

__device__ __forceinline__ void red_add_v4(float4* a, float4 v) {
    asm volatile("red.global.add.v4.f32 [%0], {%1,%2,%3,%4};"
                 :: "l"(a), "f"(v.x), "f"(v.y), "f"(v.z), "f"(v.w) : "memory");
}
__device__ __forceinline__ bool testbit(int n) {
    return (__ldg(&g_bits[n >> 5]) >> (n & 31)) & 1u;
}

// ---------------- k_raw: dedicated x-streaming dot kernel ----------
__global__ void __launch_bounds__(256, 8) k_raw(const float4* __restrict__ x4,
                                                const float4* __restrict__ pw4) {
    if (blockIdx.x == 0 && threadIdx.x == 0) g_n2 = 0;
    int gw = (blockIdx.x * blockDim.x + threadIdx.x) >> 5;
    int lane = threadIdx.x & 31;
    int nw = (gridDim.x * blockDim.x) >> 5;
    float4 w = pw4[lane];
    for (int n0 = gw * 4; n0 < NN; n0 += nw * 4) {
        float s0 = 0.f, s1 = 0.f, s2 = 0.f, s3 = 0.f;
        int lim = NN - n0;
        const float4* base = &x4[(size_t)n0 * 32 + lane];
        float4 v0 = __ldcs(base);
        s0 = v0.x * w.x + v0.y * w.y + v0.z * w.z + v0.w * w.w;
        if (lim > 1) { float4 v = __ldcs(base + 32);  s1 = v.x * w.x + v.y * w.y + v.z * w.z + v.w * w.w; }
        if (lim > 2) { float4 v = __ldcs(base + 64);  s2 = v.x * w.x + v.y * w.y + v.z * w.z + v.w * w.w; }
        if (lim > 3) { float4 v = __ldcs(base + 96);  s3 = v.x * w.x + v.y * w.y + v.z * w.z + v.w * w.w; }
        #pragma unroll
        for (int o = 16; o; o >>= 1) {
            s0 += __shfl_down_sync(0xffffffffu, s0, o);
            s1 += __shfl_down_sync(0xffffffffu, s1, o);
            s2 += __shfl_down_sync(0xffffffffu, s2, o);
            s3 += __shfl_down_sync(0xffffffffu, s3, o);
        }
        if (lane == 0) {
            g_raw[n0] = s0;
            if (lim > 1) g_raw[n0 + 1] = s1;
            if (lim > 2) g_raw[n0 + 2] = s2;
            if (lim > 3) g_raw[n0 + 3] = s3;
        }
    }
}

// ---------------- k_soft: per-graph softmax/topk over precomputed raw ----------
__global__ void k_soft(const int* __restrict__ batch, const float* __restrict__ attn) {
    int b = blockIdx.x;
    int t = threadIdx.x;
    __shared__ float sraw[1024];
    __shared__ float red[256];
    __shared__ int s_se[2];
    __shared__ int s_kcnt;
    if (t == 0) s_kcnt = 0;
    if (t < 2) {
        int target = b + t;
        int lo = 0, hi = NN;
        while (lo < hi) { int mid = (lo + hi) >> 1; if (batch[mid] < target) lo = mid + 1; else hi = mid; }
        s_se[t] = lo;
    }
    __syncthreads();
    int start = s_se[0];
    int len = s_se[1] - start;

    for (int q = t; q < len; q += 256) sraw[q] = g_raw[start + q];
    __syncthreads();

    float m = -INFINITY;
    for (int q = t; q < len; q += 256) m = fmaxf(m, sraw[q]);
    red[t] = m; __syncthreads();
    for (int o = 128; o; o >>= 1) { if (t < o) red[t] = fmaxf(red[t], red[t + o]); __syncthreads(); }
    m = red[0]; __syncthreads();

    float sum = 0.f;
    for (int q = t; q < len; q += 256) sum += expf(sraw[q] - m);
    red[t] = sum; __syncthreads();
    for (int o = 128; o; o >>= 1) { if (t < o) red[t] += red[t + o]; __syncthreads(); }
    float z = red[0]; __syncthreads();

    float smax = 1.0f / z;   // score of the argmax node (exp(0)/z)
    float thresh = fminf(smax - 1e-7f, 0.05f);

    float kl = 0.f, cnt = 0.f;
    for (int q = t; q < len; q += 256) {
        float s = expf(sraw[q] - m) / z;
        int node = start + q;
        if (s > thresh) {
            cnt += 1.f;
            float a = attn[node];
            kl += a * (logf(a) - logf(s + 1e-14f));
            g_score[node] = s;
            int slot = atomicAdd(&s_kcnt, 1);
            if (slot < KMAX) {
                g_kept[b * KMAX + slot] = node;
                atomicOr(&g_bits[node >> 5], 1u << (node & 31));
                float4 zz = make_float4(0.f, 0.f, 0.f, 0.f);
                float4* a1 = &g_agg1[(size_t)node * 32];
                #pragma unroll
                for (int qq = 0; qq < 32; qq++) a1[qq] = zz;
            }
        }
    }
    red[t] = kl; __syncthreads();
    for (int o = 128; o; o >>= 1) { if (t < o) red[t] += red[t + o]; __syncthreads(); }
    if (t == 0) g_klval[b] = red[0];
    __syncthreads();
    red[t] = cnt; __syncthreads();
    for (int o = 128; o; o >>= 1) { if (t < o) red[t] += red[t + o]; __syncthreads(); }
    if (t == 0) {
        g_cntval[b] = red[0];
        g_keptcnt[b] = (s_kcnt < KMAX) ? s_kcnt : KMAX;
    }
}

// ---------------- k_edges: scatter-1 + both-kept edge list + ratio ----------
#define EPB 1024
__global__ void k_edges(const int* __restrict__ ei, const float4* __restrict__ x4,
                        float* __restrict__ out) {
    __shared__ int list[EPB];
    __shared__ int scnt;
    __shared__ float rsum[256];
    if (threadIdx.x == 0) scnt = 0;
    __syncthreads();
    int q = blockIdx.x * 256 + threadIdx.x;
    if (q < EE / 4) {
        int4 d4 = ((const int4*)(ei + EE))[q];
        int e0 = q * 4;
        int dd[4] = {d4.x, d4.y, d4.z, d4.w};
        #pragma unroll
        for (int k = 0; k < 4; k++) {
            int d = dd[k];
            if (testbit(d)) {
                int e = e0 + k;
                int p = atomicAdd(&scnt, 1);
                list[p] = e;
                int s = ei[e];
                if (testbit(s)) {
                    int w = atomicAdd(&g_n2, 1);
                    g_elist[w] = e;
                }
            }
        }
    }
    __syncthreads();
    int nk = scnt;
    int wid = threadIdx.x >> 5;
    int lane = threadIdx.x & 31;
    for (int i = wid; i < nk; i += 8) {
        int ee = list[i];
        int s = ei[ee];
        int d = ei[EE + ee];
        red_add_v4(&g_agg1[(size_t)d * 32 + lane], x4[(size_t)s * 32 + lane]);
    }
    if (blockIdx.x == 0) {
        __syncthreads();
        rsum[threadIdx.x] = g_cntval[threadIdx.x] + g_cntval[threadIdx.x + 256];
        __syncthreads();
        for (int o = 128; o; o >>= 1) { if (threadIdx.x < o) rsum[threadIdx.x] += rsum[threadIdx.x + o]; __syncthreads(); }
        if (threadIdx.x == 0) out[2 * GG] = rsum[0] / (float)NN;
    }
}

// ---------------- fused GIN1 + scatter2(local) + GIN2 + outputs -------------
// 256 threads = 64 outputs (j) x 4 k-quarters (q). Block-uniform control flow
// around every __syncthreads(). 8-deep register prefetch on all weight loads.

// MLP 128->64(relu)->64(relu), scaled; writes/accumulates into dst[64].
__device__ __forceinline__ void mlp128(
    const float* sv, float sp[4][HH], float* sh1,
    const float* __restrict__ Wa, const float* __restrict__ ba,
    const float* __restrict__ Wb, const float* __restrict__ bb,
    int t, int j, int q, float scale, float* dst, bool accumulate)
{
    float acc = (q == 0) ? __ldg(&ba[j]) : 0.f;
    const float* wp = Wa + (size_t)(q * 32) * HH + j;
    #pragma unroll
    for (int kb = 0; kb < 4; kb++) {
        float w[8];
        #pragma unroll
        for (int u = 0; u < 8; u++) w[u] = __ldg(&wp[(size_t)(kb * 8 + u) * HH]);
        #pragma unroll
        for (int u = 0; u < 8; u++) acc = fmaf(sv[q * 32 + kb * 8 + u], w[u], acc);
    }
    sp[q][j] = acc;
    __syncthreads();
    if (t < HH) sh1[t] = fmaxf((sp[0][t] + sp[1][t]) + (sp[2][t] + sp[3][t]), 0.f);
    __syncthreads();
    float a2 = (q == 0) ? __ldg(&bb[j]) : 0.f;
    const float* wp2 = Wb + (size_t)(q * 16) * HH + j;
    #pragma unroll
    for (int kb = 0; kb < 2; kb++) {
        float w[8];
        #pragma unroll
        for (int u = 0; u < 8; u++) w[u] = __ldg(&wp2[(size_t)(kb * 8 + u) * HH]);
        #pragma unroll
        for (int u = 0; u < 8; u++) a2 = fmaf(sh1[q * 16 + kb * 8 + u], w[u], a2);
    }
    sp[q][j] = a2;
    __syncthreads();
    if (t < HH) {
        float o = fmaxf((sp[0][t] + sp[1][t]) + (sp[2][t] + sp[3][t]), 0.f) * scale;
        if (accumulate) dst[t] += o; else dst[t] = o;
    }
    __syncthreads();
}

// MLP 64->64(relu)->64(relu); accumulates into dst[64].
__device__ __forceinline__ void mlp64(
    const float* sv, float sp[4][HH], float* sh1,
    const float* __restrict__ Wa, const float* __restrict__ ba,
    const float* __restrict__ Wb, const float* __restrict__ bb,
    int t, int j, int q, float* dst)
{
    float acc = (q == 0) ? __ldg(&ba[j]) : 0.f;
    const float* wp = Wa + (size_t)(q * 16) * HH + j;
    #pragma unroll
    for (int kb = 0; kb < 2; kb++) {
        float w[8];
        #pragma unroll
        for (int u = 0; u < 8; u++) w[u] = __ldg(&wp[(size_t)(kb * 8 + u) * HH]);
        #pragma unroll
        for (int u = 0; u < 8; u++) acc = fmaf(sv[q * 16 + kb * 8 + u], w[u], acc);
    }
    sp[q][j] = acc;
    __syncthreads();
    if (t < HH) sh1[t] = fmaxf((sp[0][t] + sp[1][t]) + (sp[2][t] + sp[3][t]), 0.f);
    __syncthreads();
    float a2 = (q == 0) ? __ldg(&bb[j]) : 0.f;
    const float* wp2 = Wb + (size_t)(q * 16) * HH + j;
    #pragma unroll
    for (int kb = 0; kb < 2; kb++) {
        float w[8];
        #pragma unroll
        for (int u = 0; u < 8; u++) w[u] = __ldg(&wp2[(size_t)(kb * 8 + u) * HH]);
        #pragma unroll
        for (int u = 0; u < 8; u++) a2 = fmaf(sh1[q * 16 + kb * 8 + u], w[u], a2);
    }
    sp[q][j] = a2;
    __syncthreads();
    if (t < HH) dst[t] += fmaxf((sp[0][t] + sp[1][t]) + (sp[2][t] + sp[3][t]), 0.f);
    __syncthreads();
}

__global__ void __launch_bounds__(256, 4) k_gin(
    const float* __restrict__ x, const int* __restrict__ ei,
    const int* __restrict__ batch,
    const float* __restrict__ W1, const float* __restrict__ b1,
    const float* __restrict__ W2, const float* __restrict__ b2,
    const float* __restrict__ W3, const float* __restrict__ b3,
    const float* __restrict__ W4, const float* __restrict__ b4,
    const float* __restrict__ Wl, const float* __restrict__ bl,
    float* __restrict__ out)
{
    int g = blockIdx.x;
    int t = threadIdx.x;
    int j = t & 63;
    int q = t >> 6;
    __shared__ int s_kept[KMAX];
    __shared__ float s_out1[KMAX * HH];   // 8 KB
    __shared__ float sagg2[KMAX * HH];    // 8 KB
    __shared__ float sv[CC];
    __shared__ float sp[4][HH];
    __shared__ float sh1[HH];
    __shared__ float sgo[HH];
    __shared__ int s_msrc[MMAX];
    __shared__ int s_mslot[MMAX];
    __shared__ int s_nm;
    int cnt = g_keptcnt[g];
    if (t == 0) s_nm = 0;
    if (t < KMAX) s_kept[t] = (t < cnt) ? g_kept[g * KMAX + t] : -1;
    for (int i = t; i < cnt * HH; i += 256) sagg2[i] = 0.f;
    if (t < HH) sgo[t] = 0.f;
    __syncthreads();

    // Phase A: GIN1 for this graph's kept nodes -> s_out1 (never leaves smem)
    for (int s = 0; s < cnt; s++) {
        int n = s_kept[s];
        if (t < CC) sv[t] = x[(size_t)n * CC + t] + ((const float*)g_agg1)[(size_t)n * CC + t];
        __syncthreads();
        mlp128(sv, sp, sh1, W1, b1, W2, b2, t, j, q, g_score[n], &s_out1[s * HH], false);
    }

    // Phase B: block-local scatter-2. Matched both-kept edges with dst in this
    // graph; src out1 comes from s_out1 if local, else recomputed (rare).
    int n2 = g_n2;
    for (int i = t; i < n2; i += 256) {
        int e = g_elist[i];
        int d = ei[EE + e];
        if (batch[d] == g) {
            int slot = 0;
            #pragma unroll
            for (int k2 = 0; k2 < KMAX; k2++) if (s_kept[k2] == d) slot = k2;
            int p = atomicAdd(&s_nm, 1);
            if (p < MMAX) { s_msrc[p] = ei[e]; s_mslot[p] = slot; }
        }
    }
    __syncthreads();
    int nm = (s_nm < MMAX) ? s_nm : MMAX;
    for (int mI = 0; mI < nm; mI++) {
        int src = s_msrc[mI];
        int dslot = s_mslot[mI];
        int sslot = -1;
        #pragma unroll
        for (int k2 = 0; k2 < KMAX; k2++) if (s_kept[k2] == src) sslot = k2;
        if (sslot >= 0) {
            if (t < HH) sagg2[dslot * HH + t] += s_out1[sslot * HH + t];
            __syncthreads();
        } else {
            if (t < CC) sv[t] = x[(size_t)src * CC + t] + ((const float*)g_agg1)[(size_t)src * CC + t];
            __syncthreads();
            mlp128(sv, sp, sh1, W1, b1, W2, b2, t, j, q, g_score[src], &sagg2[dslot * HH], true);
        }
    }

    // Phase C: GIN2 + global_add_pool
    for (int s = 0; s < cnt; s++) {
        if (t < HH) sv[t] = s_out1[s * HH + t] + sagg2[s * HH + t];
        __syncthreads();
        mlp64(sv, sp, sh1, W3, b3, W4, b4, t, j, q, sgo);
    }

    // outputs
    if (t < HH) sp[0][t] = sgo[t] * __ldg(&Wl[t]);
    __syncthreads();
    if (t < 32) {
        float p = sp[0][t] + sp[0][t + 32];
        #pragma unroll
        for (int o = 16; o; o >>= 1) p += __shfl_down_sync(0xffffffffu, p, o);
        if (t == 0) {
            out[g] = p + bl[0];
            out[GG + g] = g_klval[g] / fmaxf(g_cntval[g], 1.0f);
        }
    }
    // self-clean kept bits so g_bits is all-zero for the next call
    if (t < cnt) {
        int n = s_kept[t];
        atomicAnd(&g_bits[n >> 5], ~(1u << (n & 31)));
    }
}

extern "C" void kernel_launch(void* const* d_in, const int* in_sizes, int n_in,
                              void* d_out, int out_size) {
    const float* x      = (const float*)d_in[0];
    const int*   ei     = (const int*)d_in[1];
    const int*   batch  = (const int*)d_in[2];
    const float* attn   = (const float*)d_in[3];
    const float* W1     = (const float*)d_in[4];
    const float* b1     = (const float*)d_in[5];
    const float* W2     = (const float*)d_in[6];
    const float* b2     = (const float*)d_in[7];
    const float* pool_w = (const float*)d_in[8];
    const float* W3     = (const float*)d_in[9];
    const float* b3     = (const float*)d_in[10];
    const float* W4     = (const float*)d_in[11];
    const float* b4     = (const float*)d_in[12];
    const float* Wl     = (const float*)d_in[13];
    const float* bl     = (const float*)d_in[14];
    float* out = (float*)d_out;

    k_raw<<<1184, 256>>>((const float4*)x, (const float4*)pool_w);
    k_soft<<<GG, 256>>>(batch, attn);
    k_edges<<<(EE + EPB - 1) / EPB, 256>>>(ei, (const float4*)x, out);
    k_gin<<<GG, 256>>>(x, ei, batch, W1, b1, W2, b2, W3, b3, W4, b4, Wl, bl, out);
}